// round 1
// baseline (speedup 1.0000x reference)
#include <cuda_runtime.h>
#include <math.h>

#define B_  8
#define C_  256
#define Hh  80
#define Ww  80
#define HW  6400
#define EPSF 1e-5f

// ---------------- scratch (device globals: no allocation allowed) ----------------
__device__ float g_qkv[(size_t)B_ * HW * 768];      // [B][HW][768]  (o = s*256 + dil*64 + c)
__device__ float g_stacked[(size_t)B_ * HW * 256];  // [B][HW][4][64]
__device__ float g_y2[(size_t)B_ * HW * 256];       // [B][HW][256]
__device__ float g_x1[(size_t)B_ * C_ * HW];        // [B][C][HW]
__device__ float g_h[(size_t)B_ * 512 * HW];        // [B][512][HW]

// ---------------- generic tiled SGEMM: C[m,n] = sum_k A[m,k]*B[k,n], batched over z ----
// MODE 0: y = acc + bias[n]                      (qkv)
// MODE 1: y = acc + bias[m] + res[m*N+n]         (proj + residual x)
// MODE 2: y = silu(acc*bnScale[m] + bnShift[m])  (mlp1)
// MODE 3: y = acc*bnScale[m] + bnShift[m] + res  (mlp2 + residual x1)
template<int MODE>
__global__ __launch_bounds__(256) void gemm_k(
    int M, int N, int K,
    const float* __restrict__ A, int sAm, int sAk, long long aB,
    const float* __restrict__ Bp, int sBk, int sBn, long long bB,
    float* __restrict__ Cp, long long cB,
    const float* __restrict__ bias,
    const float* __restrict__ res, long long rB,
    const float* __restrict__ gg, const float* __restrict__ bbp,
    const float* __restrict__ mmp, const float* __restrict__ vvp)
{
    __shared__ float As[8][128];
    __shared__ float Bs[8][128];

    const float* Ab = A  + (long long)blockIdx.z * aB;
    const float* Bb = Bp + (long long)blockIdx.z * bB;
    float*       Cb = Cp + (long long)blockIdx.z * cB;

    const int m0 = blockIdx.y * 128;
    const int n0 = blockIdx.x * 128;
    const int tid = threadIdx.x;
    const int tx = tid & 15;     // n microtile
    const int ty = tid >> 4;     // m microtile

    float acc[8][8];
#pragma unroll
    for (int i = 0; i < 8; i++)
#pragma unroll
        for (int j = 0; j < 8; j++) acc[i][j] = 0.f;

    for (int k0 = 0; k0 < K; k0 += 8) {
#pragma unroll
        for (int t = 0; t < 4; t++) {
            int idx = tid + t * 256;
            int m = idx & 127, kk = idx >> 7;
            As[kk][m] = Ab[(long long)(m0 + m) * sAm + (long long)(k0 + kk) * sAk];
        }
#pragma unroll
        for (int t = 0; t < 4; t++) {
            int idx = tid + t * 256;
            int n = idx & 127, kk = idx >> 7;
            Bs[kk][n] = Bb[(long long)(k0 + kk) * sBk + (long long)(n0 + n) * sBn];
        }
        __syncthreads();
#pragma unroll
        for (int kk = 0; kk < 8; kk++) {
            float4 a0 = *(const float4*)&As[kk][ty * 8];
            float4 a1 = *(const float4*)&As[kk][ty * 8 + 4];
            float4 b0 = *(const float4*)&Bs[kk][tx * 8];
            float4 b1 = *(const float4*)&Bs[kk][tx * 8 + 4];
            float ra[8] = {a0.x, a0.y, a0.z, a0.w, a1.x, a1.y, a1.z, a1.w};
            float rb[8] = {b0.x, b0.y, b0.z, b0.w, b1.x, b1.y, b1.z, b1.w};
#pragma unroll
            for (int i = 0; i < 8; i++)
#pragma unroll
                for (int j = 0; j < 8; j++)
                    acc[i][j] = fmaf(ra[i], rb[j], acc[i][j]);
        }
        __syncthreads();
    }

#pragma unroll
    for (int i = 0; i < 8; i++) {
        const int gm = m0 + ty * 8 + i;
        float sc = 1.f, sh = 0.f;
        if (MODE == 1) sh = bias[gm];
        if (MODE >= 2) {
            float inv = gg[gm] * rsqrtf(vvp[gm] + EPSF);
            sc = inv;
            sh = bbp[gm] - mmp[gm] * inv;
        }
        const long long rowoff = (long long)gm * N;
#pragma unroll
        for (int j = 0; j < 8; j++) {
            const int gn = n0 + tx * 8 + j;
            float y = acc[i][j];
            if (MODE == 0) y += bias[gn];
            else           y = y * sc + sh;
            if (MODE == 2) y = y / (1.f + expf(-y));  // SiLU
            if (MODE == 1 || MODE == 3)
                y += res[(long long)blockIdx.z * rB + rowoff + gn];
            Cb[rowoff + gn] = y;
        }
    }
}

// ---------------- dilated 3x3 neighborhood attention: 1 warp per (pixel, dilation) ----
__global__ __launch_bounds__(256) void attn_k(const float* __restrict__ qkv,
                                              float* __restrict__ stacked)
{
    const int gw = blockIdx.x * 8 + (threadIdx.x >> 5);
    const int lane = threadIdx.x & 31;
    const int BHW = B_ * HW;
    const int dil = gw / BHW;                 // 0..3, r = 1<<dil
    const int rem = gw - dil * BHW;
    const int b   = rem / HW;
    const int pix = rem - b * HW;
    const int y = pix / Ww, x = pix - y * Ww;
    const int r = 1 << dil;

    const float* base = qkv + (long long)b * HW * 768;
    const float* qp = base + (long long)pix * 768 + dil * 64;
    const float q0 = qp[lane], q1 = qp[lane + 32];

    float sc[9];
#pragma unroll
    for (int j = 0; j < 9; j++) {
        const int yy = y + (j / 3 - 1) * r;
        const int xx = x + (j % 3 - 1) * r;
        float s = 0.f;
        if (yy >= 0 && yy < Hh && xx >= 0 && xx < Ww) {
            const float* kp = base + (long long)(yy * Ww + xx) * 768 + 256 + dil * 64;
            s = q0 * kp[lane] + q1 * kp[lane + 32];
        }
#pragma unroll
        for (int o = 16; o > 0; o >>= 1) s += __shfl_xor_sync(0xffffffffu, s, o);
        sc[j] = s * 0.125f;                  // scale = hd^-0.5 = 1/8
    }

    float mx = sc[0];
#pragma unroll
    for (int j = 1; j < 9; j++) mx = fmaxf(mx, sc[j]);
    float p[9], sum = 0.f;
#pragma unroll
    for (int j = 0; j < 9; j++) { p[j] = expf(sc[j] - mx); sum += p[j]; }
    const float inv = 1.f / sum;

    float a0 = 0.f, a1 = 0.f;
#pragma unroll
    for (int j = 0; j < 9; j++) {
        const int yy = y + (j / 3 - 1) * r;
        const int xx = x + (j % 3 - 1) * r;
        if (yy >= 0 && yy < Hh && xx >= 0 && xx < Ww) {
            const float* vp = base + (long long)(yy * Ww + xx) * 768 + 512 + dil * 64;
            a0 += p[j] * vp[lane];
            a1 += p[j] * vp[lane + 32];
        }
    }
    float* op = stacked + ((long long)(b * HW + pix) * 4 + dil) * 64;
    op[lane]      = a0 * inv;
    op[lane + 32] = a1 * inv;
}

// ---------------- fc mixing across dilations + residual + LayerNorm(64) ----------------
__global__ __launch_bounds__(256) void fuse_ln_k(
    const float* __restrict__ stacked,
    const float* __restrict__ fcw, const float* __restrict__ fcb,
    const float* __restrict__ lng, const float* __restrict__ lnb,
    float* __restrict__ y2)
{
    const long long pix = blockIdx.x;
    const float* sp = stacked + pix * 256;
    const int t = threadIdx.x >> 6;     // dilation slot 0..3
    const int c = threadIdx.x & 63;     // channel within slot

    const float s0 = sp[c], s1 = sp[64 + c], s2 = sp[128 + c], s3 = sp[192 + c];
    const float own = (t == 0) ? s0 : (t == 1) ? s1 : (t == 2) ? s2 : s3;
    float f = fcw[t * 4 + 0] * s0 + fcw[t * 4 + 1] * s1 +
              fcw[t * 4 + 2] * s2 + fcw[t * 4 + 3] * s3 + fcb[t] + own;

    float sum = f, sq = f * f;
#pragma unroll
    for (int o = 16; o > 0; o >>= 1) {
        sum += __shfl_xor_sync(0xffffffffu, sum, o);
        sq  += __shfl_xor_sync(0xffffffffu, sq, o);
    }
    __shared__ float ssum[8], ssq[8];
    const int w = threadIdx.x >> 5;
    if ((threadIdx.x & 31) == 0) { ssum[w] = sum; ssq[w] = sq; }
    __syncthreads();
    const float tot  = ssum[2 * t] + ssum[2 * t + 1];
    const float totq = ssq[2 * t] + ssq[2 * t + 1];
    const float mu  = tot * (1.f / 64.f);
    const float var = totq * (1.f / 64.f) - mu * mu;
    const float yv = (f - mu) * rsqrtf(var + EPSF) * lng[c] + lnb[c];
    y2[pix * 256 + threadIdx.x] = yv;
}

// ---------------- launch ----------------
extern "C" void kernel_launch(void* const* d_in, const int* in_sizes, int n_in,
                              void* d_out, int out_size)
{
    const float* x      = (const float*)d_in[0];
    const float* qkv_w  = (const float*)d_in[1];
    const float* qkv_b  = (const float*)d_in[2];
    const float* fc_w   = (const float*)d_in[3];
    const float* fc_b   = (const float*)d_in[4];
    const float* ln_g   = (const float*)d_in[5];
    const float* ln_b   = (const float*)d_in[6];
    const float* proj_w = (const float*)d_in[7];
    const float* proj_b = (const float*)d_in[8];
    const float* w1     = (const float*)d_in[9];
    const float* bn1_g  = (const float*)d_in[10];
    const float* bn1_b  = (const float*)d_in[11];
    const float* bn1_m  = (const float*)d_in[12];
    const float* bn1_v  = (const float*)d_in[13];
    const float* w2     = (const float*)d_in[14];
    const float* bn2_g  = (const float*)d_in[15];
    const float* bn2_b  = (const float*)d_in[16];
    const float* bn2_m  = (const float*)d_in[17];
    const float* bn2_v  = (const float*)d_in[18];
    float* out = (float*)d_out;

    float *qkv, *stacked, *y2, *x1, *hb;
    cudaGetSymbolAddress((void**)&qkv,     g_qkv);
    cudaGetSymbolAddress((void**)&stacked, g_stacked);
    cudaGetSymbolAddress((void**)&y2,      g_y2);
    cudaGetSymbolAddress((void**)&x1,      g_x1);
    cudaGetSymbolAddress((void**)&hb,      g_h);

    dim3 blk(256);

    // 1) qkv GEMM: C[pix, o] = sum_c x[b][c][pix] * qkv_w[o][c] + qkv_b[o]
    gemm_k<0><<<dim3(768 / 128, HW / 128, B_), blk>>>(
        HW, 768, 256,
        x, 1, HW, (long long)C_ * HW,
        qkv_w, 1, 256, 0,
        qkv, (long long)HW * 768,
        qkv_b, nullptr, 0, nullptr, nullptr, nullptr, nullptr);

    // 2) attention (4 dilations)
    attn_k<<<(B_ * HW * 4) / 8, blk>>>(qkv, stacked);

    // 3) dilation-mix FC + residual + LayerNorm
    fuse_ln_k<<<B_ * HW, blk>>>(stacked, fc_w, fc_b, ln_g, ln_b, y2);

    // 4) proj GEMM + residual x -> x1 [B][C][HW]
    gemm_k<1><<<dim3(HW / 128, 256 / 128, B_), blk>>>(
        256, HW, 256,
        proj_w, 256, 1, 0,
        y2, 1, 256, (long long)HW * 256,
        x1, (long long)C_ * HW,
        proj_b, x, (long long)C_ * HW, nullptr, nullptr, nullptr, nullptr);

    // 5) MLP1: h = silu(bn1(w1 @ x1)) -> [B][512][HW]
    gemm_k<2><<<dim3(HW / 128, 512 / 128, B_), blk>>>(
        512, HW, 256,
        w1, 256, 1, 0,
        x1, HW, 1, (long long)C_ * HW,
        hb, (long long)512 * HW,
        nullptr, nullptr, 0, bn1_g, bn1_b, bn1_m, bn1_v);

    // 6) MLP2: out = x1 + bn2(w2 @ h)
    gemm_k<3><<<dim3(HW / 128, 256 / 128, B_), blk>>>(
        256, HW, 512,
        w2, 512, 1, 0,
        hb, HW, 1, (long long)512 * HW,
        out, (long long)C_ * HW,
        nullptr, x1, (long long)C_ * HW, bn2_g, bn2_b, bn2_m, bn2_v);
}

// round 3
// speedup vs baseline: 3.8260x; 3.8260x over previous
#include <cuda_runtime.h>
#include <cstdint>
#include <math.h>

#define B_  8
#define C_  256
#define Hh  80
#define Ww  80
#define HW  6400
#define NPIX 51200
#define EPSF 1e-5f

#define KC 32
#define TSTR 36                 // smem row stride in floats (144B, 16B-aligned)
#define ASZ (128*TSTR)          // floats per stage per operand
#define SMEM_BYTES (4*ASZ*4)    // 2 stages x (A+B) = 73728 B

// ---------------- scratch ----------------
__device__ float g_xT [(size_t)NPIX*256];   // tf32-rounded (GEMM A)
__device__ float g_xTf[(size_t)NPIX*256];   // full fp32 (residual)
__device__ float g_qkv[(size_t)NPIX*768];
__device__ float g_stk[(size_t)NPIX*256];
__device__ float g_y2 [(size_t)NPIX*256];
__device__ float g_x1r[(size_t)NPIX*256];   // tf32-rounded (GEMM A)
__device__ float g_x1f[(size_t)NPIX*256];   // full fp32 (residual)
__device__ float g_h  [(size_t)NPIX*512];
__device__ float g_w  [524288];             // rounded weights: qkvw|projw|w1|w2

// ---------------- helpers ----------------
__device__ __forceinline__ float rna(float x){ float r; asm("cvt.rna.tf32.f32 %0, %1;" : "=f"(r) : "f"(x)); return r; }
__device__ __forceinline__ uint32_t s2u(const void* p){
    uint32_t a; asm("{ .reg .u64 t; cvta.to.shared.u64 t, %1; cvt.u32.u64 %0, t; }" : "=r"(a) : "l"(p)); return a;
}
#define CPA16(d,s) asm volatile("cp.async.cg.shared.global [%0], [%1], 16;" :: "r"(d), "l"(s))
#define CPCOMMIT() asm volatile("cp.async.commit_group;" ::: "memory")
#define CPWAIT(n)  asm volatile("cp.async.wait_group %0;" :: "n"(n) : "memory")

__device__ __forceinline__ void mma8(float* d, const uint32_t* a, uint32_t b0, uint32_t b1){
    asm volatile("mma.sync.aligned.m16n8k8.row.col.f32.tf32.tf32.f32 "
        "{%0,%1,%2,%3}, {%4,%5,%6,%7}, {%8,%9}, {%0,%1,%2,%3};"
        : "+f"(d[0]), "+f"(d[1]), "+f"(d[2]), "+f"(d[3])
        : "r"(a[0]), "r"(a[1]), "r"(a[2]), "r"(a[3]), "r"(b0), "r"(b1));
}

// ---------------- tf32 mma.sync GEMM: D[pix, n] = A[pix,:] . Bw[n,:] ----------------
// MODE 0: y = acc + bias[n]                       -> qkv (Cstride 768)
// MODE 1: Cp = rna(acc+bias+res), Cp2 = full      -> x1r / x1f
// MODE 2: y = rna(silu(acc*sc+sh))                -> h   (Cstride 512)
// MODE 3: y = acc*sc+sh + res -> out[b][n][pixl]  (smem-staged transposed store)
template<int MODE>
__global__ __launch_bounds__(256, 2) void gemm_mma(
    const float* __restrict__ A, const float* __restrict__ Bw,
    float* __restrict__ Cp, float* __restrict__ Cp2, int Ktot, int Cstride,
    const float* __restrict__ bias, const float* __restrict__ res,
    const float* __restrict__ gg, const float* __restrict__ bb,
    const float* __restrict__ mm, const float* __restrict__ vv)
{
    extern __shared__ float smemf[];
    const uint32_t smem_b = s2u(smemf);

    const int tid  = threadIdx.x;
    const int wid  = tid >> 5;
    const int lane = tid & 31;
    const int wm   = wid & 1;        // 2 warps in M
    const int wn   = wid >> 1;       // 4 warps in N
    const int lr   = lane >> 2;      // 0..7
    const int lc   = lane & 3;       // 0..3
    const int m0   = blockIdx.y * 128;
    const int n0   = blockIdx.x * 128;

    float d[4][4][4];
#pragma unroll
    for (int i = 0; i < 4; i++)
#pragma unroll
        for (int j = 0; j < 4; j++)
#pragma unroll
            for (int e = 0; e < 4; e++) d[i][j][e] = 0.f;

    const int nch = Ktot / KC;

    auto load = [&](int cc){
        const int s = cc & 1;
        const float* Ab = A + (size_t)m0 * Ktot + cc*KC;
        const uint32_t da = smem_b + s*ASZ*4;
#pragma unroll
        for (int t = 0; t < 4; t++){
            int i = tid + t*256;
            int r = i >> 3, c = i & 7;
            CPA16(da + r*TSTR*4 + c*16, (const void*)(Ab + (size_t)r*Ktot + c*4));
        }
        const float* Bb = Bw + (size_t)n0 * Ktot + cc*KC;
        const uint32_t db = smem_b + (2 + s)*ASZ*4;
#pragma unroll
        for (int t = 0; t < 4; t++){
            int i = tid + t*256;
            int r = i >> 3, c = i & 7;
            CPA16(db + r*TSTR*4 + c*16, (const void*)(Bb + (size_t)r*Ktot + c*4));
        }
        CPCOMMIT();
    };

    load(0);
    if (nch > 1) load(1);

    for (int cc = 0; cc < nch; cc++){
        if (cc + 1 < nch) CPWAIT(1); else CPWAIT(0);
        __syncthreads();

        const uint32_t* au = (const uint32_t*)(smemf + (cc&1)*ASZ)
                             + (wm*64 + lr)*TSTR + lc;
        const uint32_t* bu = (const uint32_t*)(smemf + (2 + (cc&1))*ASZ)
                             + (wn*32 + lr)*TSTR + lc;
#pragma unroll
        for (int kk = 0; kk < 4; kk++){
            uint32_t af[4][4];
#pragma unroll
            for (int mi = 0; mi < 4; mi++){
                const uint32_t* p = au + mi*16*TSTR + kk*8;
                af[mi][0] = p[0];
                af[mi][1] = p[8*TSTR];
                af[mi][2] = p[4];
                af[mi][3] = p[8*TSTR + 4];
            }
#pragma unroll
            for (int ni = 0; ni < 4; ni++){
                const uint32_t* p = bu + ni*8*TSTR + kk*8;
                uint32_t b0 = p[0], b1 = p[4];
#pragma unroll
                for (int mi = 0; mi < 4; mi++)
                    mma8(d[mi][ni], af[mi], b0, b1);
            }
        }
        __syncthreads();
        if (cc + 2 < nch) load(cc + 2);
    }

    // ---------------- epilogue ----------------
    const int lc2 = lc * 2;

    if (MODE != 3){
        float bv0[4], bv1[4], sc0[4], sc1[4], sh0[4], sh1[4];
#pragma unroll
        for (int ni = 0; ni < 4; ni++){
            const int gc = n0 + wn*32 + ni*8 + lc2;
            if (MODE <= 1){ bv0[ni] = bias[gc]; bv1[ni] = bias[gc+1]; }
            if (MODE == 2){
                float i0 = gg[gc]   * rsqrtf(vv[gc]   + EPSF);
                float i1 = gg[gc+1] * rsqrtf(vv[gc+1] + EPSF);
                sc0[ni] = i0; sh0[ni] = bb[gc]   - mm[gc]  *i0;
                sc1[ni] = i1; sh1[ni] = bb[gc+1] - mm[gc+1]*i1;
            }
        }
#pragma unroll
        for (int mi = 0; mi < 4; mi++){
#pragma unroll
            for (int rr = 0; rr < 2; rr++){
                const int r = m0 + wm*64 + mi*16 + lr + rr*8;
                float* crow = Cp + (size_t)r*Cstride + n0 + wn*32;
                const float* rrow = (MODE == 1) ? res + (size_t)r*256 + n0 + wn*32 : (const float*)0;
                float* crow2 = (MODE == 1) ? Cp2 + (size_t)r*256 + n0 + wn*32 : (float*)0;
#pragma unroll
                for (int ni = 0; ni < 4; ni++){
                    const int c = ni*8 + lc2;
                    float v0 = d[mi][ni][rr*2+0];
                    float v1 = d[mi][ni][rr*2+1];
                    if (MODE == 0){
                        v0 += bv0[ni]; v1 += bv1[ni];
                        *(float2*)(crow + c) = make_float2(v0, v1);
                    } else if (MODE == 1){
                        v0 += bv0[ni] + rrow[c];
                        v1 += bv1[ni] + rrow[c+1];
                        *(float2*)(crow2 + c) = make_float2(v0, v1);
                        *(float2*)(crow  + c) = make_float2(rna(v0), rna(v1));
                    } else { // MODE 2
                        v0 = v0*sc0[ni] + sh0[ni];
                        v1 = v1*sc1[ni] + sh1[ni];
                        v0 = v0 / (1.f + expf(-v0));
                        v1 = v1 / (1.f + expf(-v1));
                        *(float2*)(crow + c) = make_float2(rna(v0), rna(v1));
                    }
                }
            }
        }
    } else {
        // MODE 3: bn2 + residual, then smem-transposed coalesced store to [b][c][hw]
        __syncthreads();
        float* stg = smemf + wid * (64*33);
#pragma unroll
        for (int ni = 0; ni < 4; ni++){
            const int gc = n0 + wn*32 + ni*8 + lc2;
            const float i0 = gg[gc]   * rsqrtf(vv[gc]   + EPSF);
            const float i1 = gg[gc+1] * rsqrtf(vv[gc+1] + EPSF);
            const float s0 = bb[gc]   - mm[gc]  *i0;
            const float s1 = bb[gc+1] - mm[gc+1]*i1;
#pragma unroll
            for (int mi = 0; mi < 4; mi++){
#pragma unroll
                for (int rr = 0; rr < 2; rr++){
                    const int lrow = mi*16 + lr + rr*8;
                    const int grow = m0 + wm*64 + lrow;
                    const float* rp = res + (size_t)grow*256 + gc;
                    stg[lrow*33 + ni*8 + lc2]     = d[mi][ni][rr*2+0]*i0 + s0 + rp[0];
                    stg[lrow*33 + ni*8 + lc2 + 1] = d[mi][ni][rr*2+1]*i1 + s1 + rp[1];
                }
            }
        }
        __syncwarp();
        const int pix0 = m0 + wm*64;
        const int bidx = pix0 / HW;
        const int pixl = pix0 - bidx*HW;
        float* ob = Cp + (size_t)bidx*C_*HW + pixl;
#pragma unroll
        for (int n = 0; n < 32; n++){
            const int gc = n0 + wn*32 + n;
            ob[(size_t)gc*HW + lane]      = stg[lane*33 + n];
            ob[(size_t)gc*HW + lane + 32] = stg[(lane+32)*33 + n];
        }
    }
}

// ---------------- transpose x [B][C][HW] -> xT (rounded) + xTf (full) ----------------
__global__ __launch_bounds__(256) void transpose_k(const float* __restrict__ x,
                                                   float* __restrict__ xT,
                                                   float* __restrict__ xTf)
{
    __shared__ float t[32][33];
    const int b = blockIdx.z;
    const int hw0 = blockIdx.x * 32, c0 = blockIdx.y * 32;
    const int tx = threadIdx.x, ty = threadIdx.y;
#pragma unroll
    for (int i = 0; i < 4; i++){
        int c = c0 + ty + i*8;
        t[ty + i*8][tx] = x[(size_t)b*C_*HW + (size_t)c*HW + hw0 + tx];
    }
    __syncthreads();
#pragma unroll
    for (int i = 0; i < 4; i++){
        int hw = hw0 + ty + i*8;
        float v = t[tx][ty + i*8];
        xT [(size_t)(b*HW + hw)*256 + c0 + tx] = rna(v);
        xTf[(size_t)(b*HW + hw)*256 + c0 + tx] = v;
    }
}

// ---------------- round weights ----------------
__global__ __launch_bounds__(256) void roundw_k(
    const float* __restrict__ qkvw, const float* __restrict__ projw,
    const float* __restrict__ w1, const float* __restrict__ w2, float* __restrict__ gw)
{
    int i = blockIdx.x * 256 + threadIdx.x;
    float v;
    if (i < 196608)      v = qkvw[i];
    else if (i < 262144) v = projw[i - 196608];
    else if (i < 393216) v = w1[i - 262144];
    else                 v = w2[i - 393216];
    gw[i] = rna(v);
}

// ---------------- dilated 3x3 neighborhood attention ----------------
__global__ __launch_bounds__(256) void attn_k(const float* __restrict__ qkv,
                                              float* __restrict__ stacked)
{
    const int gw = blockIdx.x * 8 + (threadIdx.x >> 5);
    const int lane = threadIdx.x & 31;
    const int BHW = B_ * HW;
    const int dil = gw / BHW;
    const int rem = gw - dil * BHW;
    const int b   = rem / HW;
    const int pix = rem - b * HW;
    const int y = pix / Ww, x = pix - y * Ww;
    const int r = 1 << dil;

    const float* base = qkv + (size_t)b * HW * 768;
    const float* qp = base + (size_t)pix * 768 + dil * 64;
    const float q0 = qp[lane], q1 = qp[lane + 32];

    float sc[9];
#pragma unroll
    for (int j = 0; j < 9; j++){
        const int yy = y + (j/3 - 1) * r;
        const int xx = x + (j%3 - 1) * r;
        float s = 0.f;
        if (yy >= 0 && yy < Hh && xx >= 0 && xx < Ww){
            const float* kp = base + (size_t)(yy*Ww + xx)*768 + 256 + dil*64;
            s = q0 * kp[lane] + q1 * kp[lane + 32];
        }
#pragma unroll
        for (int o = 16; o > 0; o >>= 1) s += __shfl_xor_sync(0xffffffffu, s, o);
        sc[j] = s * 0.125f;
    }
    float mx = sc[0];
#pragma unroll
    for (int j = 1; j < 9; j++) mx = fmaxf(mx, sc[j]);
    float p[9], sum = 0.f;
#pragma unroll
    for (int j = 0; j < 9; j++){ p[j] = expf(sc[j] - mx); sum += p[j]; }
    const float inv = 1.f / sum;

    float a0 = 0.f, a1 = 0.f;
#pragma unroll
    for (int j = 0; j < 9; j++){
        const int yy = y + (j/3 - 1) * r;
        const int xx = x + (j%3 - 1) * r;
        if (yy >= 0 && yy < Hh && xx >= 0 && xx < Ww){
            const float* vp = base + (size_t)(yy*Ww + xx)*768 + 512 + dil*64;
            a0 += p[j] * vp[lane];
            a1 += p[j] * vp[lane + 32];
        }
    }
    float* op = stacked + ((size_t)(b*HW + pix)*4 + dil)*64;
    op[lane]      = a0 * inv;
    op[lane + 32] = a1 * inv;
}

// ---------------- fc mix + residual + LayerNorm(64), tf32-rounded out ----------------
__global__ __launch_bounds__(256) void fuse_ln_k(
    const float* __restrict__ stacked,
    const float* __restrict__ fcw, const float* __restrict__ fcb,
    const float* __restrict__ lng, const float* __restrict__ lnb,
    float* __restrict__ y2)
{
    const size_t pix = blockIdx.x;
    const float* sp = stacked + pix * 256;
    const int t = threadIdx.x >> 6;
    const int c = threadIdx.x & 63;

    const float s0 = sp[c], s1 = sp[64 + c], s2 = sp[128 + c], s3 = sp[192 + c];
    const float own = (t == 0) ? s0 : (t == 1) ? s1 : (t == 2) ? s2 : s3;
    float f = fcw[t*4+0]*s0 + fcw[t*4+1]*s1 + fcw[t*4+2]*s2 + fcw[t*4+3]*s3 + fcb[t] + own;

    float sum = f, sq = f*f;
#pragma unroll
    for (int o = 16; o > 0; o >>= 1){
        sum += __shfl_xor_sync(0xffffffffu, sum, o);
        sq  += __shfl_xor_sync(0xffffffffu, sq,  o);
    }
    __shared__ float ssum[8], ssq[8];
    const int w = threadIdx.x >> 5;
    if ((threadIdx.x & 31) == 0){ ssum[w] = sum; ssq[w] = sq; }
    __syncthreads();
    const float tot  = ssum[2*t] + ssum[2*t+1];
    const float totq = ssq[2*t]  + ssq[2*t+1];
    const float mu  = tot * (1.f/64.f);
    const float var = totq * (1.f/64.f) - mu*mu;
    const float yv = (f - mu) * rsqrtf(var + EPSF) * lng[c] + lnb[c];
    y2[pix*256 + threadIdx.x] = rna(yv);
}

// ---------------- launch ----------------
extern "C" void kernel_launch(void* const* d_in, const int* in_sizes, int n_in,
                              void* d_out, int out_size)
{
    const float* x      = (const float*)d_in[0];
    const float* qkv_w  = (const float*)d_in[1];
    const float* qkv_b  = (const float*)d_in[2];
    const float* fc_w   = (const float*)d_in[3];
    const float* fc_b   = (const float*)d_in[4];
    const float* ln_g   = (const float*)d_in[5];
    const float* ln_b   = (const float*)d_in[6];
    const float* proj_w = (const float*)d_in[7];
    const float* proj_b = (const float*)d_in[8];
    const float* w1     = (const float*)d_in[9];
    const float* bn1_g  = (const float*)d_in[10];
    const float* bn1_b  = (const float*)d_in[11];
    const float* bn1_m  = (const float*)d_in[12];
    const float* bn1_v  = (const float*)d_in[13];
    const float* w2     = (const float*)d_in[14];
    const float* bn2_g  = (const float*)d_in[15];
    const float* bn2_b  = (const float*)d_in[16];
    const float* bn2_m  = (const float*)d_in[17];
    const float* bn2_v  = (const float*)d_in[18];
    float* out = (float*)d_out;

    float *xT, *xTf, *qkv, *stk, *y2, *x1r, *x1f, *hb, *gw;
    cudaGetSymbolAddress((void**)&xT,  g_xT);
    cudaGetSymbolAddress((void**)&xTf, g_xTf);
    cudaGetSymbolAddress((void**)&qkv, g_qkv);
    cudaGetSymbolAddress((void**)&stk, g_stk);
    cudaGetSymbolAddress((void**)&y2,  g_y2);
    cudaGetSymbolAddress((void**)&x1r, g_x1r);
    cudaGetSymbolAddress((void**)&x1f, g_x1f);
    cudaGetSymbolAddress((void**)&hb,  g_h);
    cudaGetSymbolAddress((void**)&gw,  g_w);

    cudaFuncSetAttribute(gemm_mma<0>, cudaFuncAttributeMaxDynamicSharedMemorySize, SMEM_BYTES);
    cudaFuncSetAttribute(gemm_mma<1>, cudaFuncAttributeMaxDynamicSharedMemorySize, SMEM_BYTES);
    cudaFuncSetAttribute(gemm_mma<2>, cudaFuncAttributeMaxDynamicSharedMemorySize, SMEM_BYTES);
    cudaFuncSetAttribute(gemm_mma<3>, cudaFuncAttributeMaxDynamicSharedMemorySize, SMEM_BYTES);

    roundw_k<<<2048, 256>>>(qkv_w, proj_w, w1, w2, gw);
    transpose_k<<<dim3(HW/32, C_/32, B_), dim3(32, 8)>>>(x, xT, xTf);

    // 1) qkv = xT @ qkv_w^T + b : [51200][768]
    gemm_mma<0><<<dim3(6, 400), 256, SMEM_BYTES>>>(
        xT, gw, qkv, nullptr, 256, 768, qkv_b, nullptr, nullptr, nullptr, nullptr, nullptr);

    // 2) attention
    attn_k<<<(B_*HW*4)/8, 256>>>(qkv, stk);

    // 3) fc mix + residual + LN
    fuse_ln_k<<<NPIX, 256>>>(stk, fc_w, fc_b, ln_g, ln_b, y2);

    // 4) x1 = y2 @ proj_w^T + proj_b + x : rounded -> x1r, full -> x1f
    gemm_mma<1><<<dim3(2, 400), 256, SMEM_BYTES>>>(
        y2, gw + 196608, x1r, x1f, 256, 256, proj_b, xTf, nullptr, nullptr, nullptr, nullptr);

    // 5) h = silu(bn1(x1 @ w1^T)) : [51200][512]
    gemm_mma<2><<<dim3(4, 400), 256, SMEM_BYTES>>>(
        x1r, gw + 262144, hb, nullptr, 256, 512, nullptr, nullptr, bn1_g, bn1_b, bn1_m, bn1_v);

    // 6) out = x1 + bn2(h @ w2^T) -> [B][C][HW]
    gemm_mma<3><<<dim3(2, 400), 256, SMEM_BYTES>>>(
        hb, gw + 393216, out, nullptr, 512, 256, nullptr, x1f, bn2_g, bn2_b, bn2_m, bn2_v);
}

// round 4
// speedup vs baseline: 3.9684x; 1.0372x over previous
#include <cuda_runtime.h>
#include <cstdint>
#include <math.h>

#define B_  8
#define C_  256
#define Hh  80
#define Ww  80
#define HW  6400
#define NPIX 51200
#define EPSF 1e-5f

#define KC 32
#define STAGES 3
#define TSTR 36                 // smem row stride in floats (144B, 16B-aligned)
#define ASZ (128*TSTR)          // floats per stage per operand
#define SMEM_BYTES (STAGES*2*ASZ*4)   // 3 stages x (A+B) = 110592 B

// ---------------- scratch ----------------
__device__ float g_xT [(size_t)NPIX*256];   // tf32-rounded (GEMM A)
__device__ float g_xTf[(size_t)NPIX*256];   // full fp32 (residual)
__device__ float g_qkv[(size_t)NPIX*768];
__device__ float g_y2 [(size_t)NPIX*256];
__device__ float g_x1r[(size_t)NPIX*256];   // tf32-rounded (GEMM A)
__device__ float g_x1f[(size_t)NPIX*256];   // full fp32 (residual)
__device__ float g_h  [(size_t)NPIX*512];
__device__ float g_w  [524288];             // rounded weights: qkvw|projw|w1|w2

// ---------------- helpers ----------------
__device__ __forceinline__ float rna(float x){ float r; asm("cvt.rna.tf32.f32 %0, %1;" : "=f"(r) : "f"(x)); return r; }
__device__ __forceinline__ uint32_t s2u(const void* p){
    uint32_t a; asm("{ .reg .u64 t; cvta.to.shared.u64 t, %1; cvt.u32.u64 %0, t; }" : "=r"(a) : "l"(p)); return a;
}
#define CPA16(d,s) asm volatile("cp.async.cg.shared.global [%0], [%1], 16;" :: "r"(d), "l"(s))
#define CPCOMMIT() asm volatile("cp.async.commit_group;" ::: "memory")
#define CPWAIT(n)  asm volatile("cp.async.wait_group %0;" :: "n"(n) : "memory")

__device__ __forceinline__ void mma8(float* d, const uint32_t* a, uint32_t b0, uint32_t b1){
    asm volatile("mma.sync.aligned.m16n8k8.row.col.f32.tf32.tf32.f32 "
        "{%0,%1,%2,%3}, {%4,%5,%6,%7}, {%8,%9}, {%0,%1,%2,%3};"
        : "+f"(d[0]), "+f"(d[1]), "+f"(d[2]), "+f"(d[3])
        : "r"(a[0]), "r"(a[1]), "r"(a[2]), "r"(a[3]), "r"(b0), "r"(b1));
}

// ---------------- tf32 mma.sync GEMM: D[pix, n] = A[pix,:] . Bw[n,:] ----------------
// MODE 0: y = acc + bias[n]                       -> qkv (Cstride 768)
// MODE 1: Cp = rna(acc+bias+res), Cp2 = full      -> x1r / x1f
// MODE 2: y = rna(silu(acc*sc+sh))                -> h   (Cstride 512)
// MODE 3: y = acc*sc+sh + res -> out[b][n][pixl]  (smem-staged transposed store)
template<int MODE>
__global__ __launch_bounds__(256, 2) void gemm_mma(
    const float* __restrict__ A, const float* __restrict__ Bw,
    float* __restrict__ Cp, float* __restrict__ Cp2, int Ktot, int Cstride,
    const float* __restrict__ bias, const float* __restrict__ res,
    const float* __restrict__ gg, const float* __restrict__ bb,
    const float* __restrict__ mm, const float* __restrict__ vv)
{
    extern __shared__ float smemf[];
    const uint32_t smem_b = s2u(smemf);

    const int tid  = threadIdx.x;
    const int wid  = tid >> 5;
    const int lane = tid & 31;
    const int wm   = wid & 1;        // 2 warps in M
    const int wn   = wid >> 1;       // 4 warps in N
    const int lr   = lane >> 2;      // 0..7
    const int lc   = lane & 3;       // 0..3
    const int m0   = blockIdx.y * 128;
    const int n0   = blockIdx.x * 128;

    float d[4][4][4];
#pragma unroll
    for (int i = 0; i < 4; i++)
#pragma unroll
        for (int j = 0; j < 4; j++)
#pragma unroll
            for (int e = 0; e < 4; e++) d[i][j][e] = 0.f;

    const int nch = Ktot / KC;

    auto load = [&](int cc){
        const int s = cc % STAGES;
        const float* Ab = A + (size_t)m0 * Ktot + cc*KC;
        const uint32_t da = smem_b + (2*s)*ASZ*4;
#pragma unroll
        for (int t = 0; t < 4; t++){
            int i = tid + t*256;
            int r = i >> 3, c = i & 7;
            CPA16(da + r*TSTR*4 + c*16, (const void*)(Ab + (size_t)r*Ktot + c*4));
        }
        const float* Bb = Bw + (size_t)n0 * Ktot + cc*KC;
        const uint32_t db = smem_b + (2*s+1)*ASZ*4;
#pragma unroll
        for (int t = 0; t < 4; t++){
            int i = tid + t*256;
            int r = i >> 3, c = i & 7;
            CPA16(db + r*TSTR*4 + c*16, (const void*)(Bb + (size_t)r*Ktot + c*4));
        }
        CPCOMMIT();
    };

    load(0);
    load(1);

    for (int cc = 0; cc < nch; cc++){
        if (cc + 2 < nch) load(cc + 2);
        const int rem = nch - 1 - cc;
        if (rem >= 2)      CPWAIT(2);
        else if (rem == 1) CPWAIT(1);
        else               CPWAIT(0);
        __syncthreads();

        const int s = cc % STAGES;
        const uint32_t* au = (const uint32_t*)(smemf + (2*s)*ASZ)
                             + (wm*64 + lr)*TSTR + lc;
        const uint32_t* bu = (const uint32_t*)(smemf + (2*s+1)*ASZ)
                             + (wn*32 + lr)*TSTR + lc;
#pragma unroll
        for (int kk = 0; kk < 4; kk++){
            uint32_t af[4][4];
#pragma unroll
            for (int mi = 0; mi < 4; mi++){
                const uint32_t* p = au + mi*16*TSTR + kk*8;
                af[mi][0] = p[0];
                af[mi][1] = p[8*TSTR];
                af[mi][2] = p[4];
                af[mi][3] = p[8*TSTR + 4];
            }
#pragma unroll
            for (int ni = 0; ni < 4; ni++){
                const uint32_t* p = bu + ni*8*TSTR + kk*8;
                uint32_t b0 = p[0], b1 = p[4];
#pragma unroll
                for (int mi = 0; mi < 4; mi++)
                    mma8(d[mi][ni], af[mi], b0, b1);
            }
        }
        __syncthreads();
    }

    // ---------------- epilogue ----------------
    const int lc2 = lc * 2;

    if (MODE != 3){
        float bv0[4], bv1[4], sc0[4], sc1[4], sh0[4], sh1[4];
#pragma unroll
        for (int ni = 0; ni < 4; ni++){
            const int gc = n0 + wn*32 + ni*8 + lc2;
            if (MODE <= 1){ bv0[ni] = bias[gc]; bv1[ni] = bias[gc+1]; }
            if (MODE == 2){
                float i0 = gg[gc]   * rsqrtf(vv[gc]   + EPSF);
                float i1 = gg[gc+1] * rsqrtf(vv[gc+1] + EPSF);
                sc0[ni] = i0; sh0[ni] = bb[gc]   - mm[gc]  *i0;
                sc1[ni] = i1; sh1[ni] = bb[gc+1] - mm[gc+1]*i1;
            }
        }
#pragma unroll
        for (int mi = 0; mi < 4; mi++){
#pragma unroll
            for (int rr = 0; rr < 2; rr++){
                const int r = m0 + wm*64 + mi*16 + lr + rr*8;
                float* crow = Cp + (size_t)r*Cstride + n0 + wn*32;
                const float* rrow = (MODE == 1) ? res + (size_t)r*256 + n0 + wn*32 : (const float*)0;
                float* crow2 = (MODE == 1) ? Cp2 + (size_t)r*256 + n0 + wn*32 : (float*)0;
#pragma unroll
                for (int ni = 0; ni < 4; ni++){
                    const int c = ni*8 + lc2;
                    float v0 = d[mi][ni][rr*2+0];
                    float v1 = d[mi][ni][rr*2+1];
                    if (MODE == 0){
                        v0 += bv0[ni]; v1 += bv1[ni];
                        *(float2*)(crow + c) = make_float2(v0, v1);
                    } else if (MODE == 1){
                        v0 += bv0[ni] + rrow[c];
                        v1 += bv1[ni] + rrow[c+1];
                        *(float2*)(crow2 + c) = make_float2(v0, v1);
                        *(float2*)(crow  + c) = make_float2(rna(v0), rna(v1));
                    } else { // MODE 2
                        v0 = v0*sc0[ni] + sh0[ni];
                        v1 = v1*sc1[ni] + sh1[ni];
                        v0 = v0 / (1.f + expf(-v0));
                        v1 = v1 / (1.f + expf(-v1));
                        *(float2*)(crow + c) = make_float2(rna(v0), rna(v1));
                    }
                }
            }
        }
    } else {
        // MODE 3: bn2 + residual, then smem-transposed coalesced store to [b][c][hw]
        __syncthreads();
        float* stg = smemf + wid * (64*33);
#pragma unroll
        for (int ni = 0; ni < 4; ni++){
            const int gc = n0 + wn*32 + ni*8 + lc2;
            const float i0 = gg[gc]   * rsqrtf(vv[gc]   + EPSF);
            const float i1 = gg[gc+1] * rsqrtf(vv[gc+1] + EPSF);
            const float s0 = bb[gc]   - mm[gc]  *i0;
            const float s1 = bb[gc+1] - mm[gc+1]*i1;
#pragma unroll
            for (int mi = 0; mi < 4; mi++){
#pragma unroll
                for (int rr = 0; rr < 2; rr++){
                    const int lrow = mi*16 + lr + rr*8;
                    const int grow = m0 + wm*64 + lrow;
                    const float* rp = res + (size_t)grow*256 + gc;
                    stg[lrow*33 + ni*8 + lc2]     = d[mi][ni][rr*2+0]*i0 + s0 + rp[0];
                    stg[lrow*33 + ni*8 + lc2 + 1] = d[mi][ni][rr*2+1]*i1 + s1 + rp[1];
                }
            }
        }
        __syncwarp();
        const int pix0 = m0 + wm*64;
        const int bidx = pix0 / HW;
        const int pixl = pix0 - bidx*HW;
        float* ob = Cp + (size_t)bidx*C_*HW + pixl;
#pragma unroll
        for (int n = 0; n < 32; n++){
            const int gc = n0 + wn*32 + n;
            ob[(size_t)gc*HW + lane]      = stg[lane*33 + n];
            ob[(size_t)gc*HW + lane + 32] = stg[(lane+32)*33 + n];
        }
    }
}

// ---------------- transpose x [B][C][HW] -> xT (rounded) + xTf (full) ----------------
__global__ __launch_bounds__(256) void transpose_k(const float* __restrict__ x,
                                                   float* __restrict__ xT,
                                                   float* __restrict__ xTf)
{
    __shared__ float t[32][33];
    const int b = blockIdx.z;
    const int hw0 = blockIdx.x * 32, c0 = blockIdx.y * 32;
    const int tx = threadIdx.x, ty = threadIdx.y;
#pragma unroll
    for (int i = 0; i < 4; i++){
        int c = c0 + ty + i*8;
        t[ty + i*8][tx] = x[(size_t)b*C_*HW + (size_t)c*HW + hw0 + tx];
    }
    __syncthreads();
#pragma unroll
    for (int i = 0; i < 4; i++){
        int hw = hw0 + ty + i*8;
        float v = t[tx][ty + i*8];
        xT [(size_t)(b*HW + hw)*256 + c0 + tx] = rna(v);
        xTf[(size_t)(b*HW + hw)*256 + c0 + tx] = v;
    }
}

// ---------------- round weights ----------------
__global__ __launch_bounds__(256) void roundw_k(
    const float* __restrict__ qkvw, const float* __restrict__ projw,
    const float* __restrict__ w1, const float* __restrict__ w2, float* __restrict__ gw)
{
    int i = blockIdx.x * 256 + threadIdx.x;
    float v;
    if (i < 196608)      v = qkvw[i];
    else if (i < 262144) v = projw[i - 196608];
    else if (i < 393216) v = w1[i - 262144];
    else                 v = w2[i - 393216];
    gw[i] = rna(v);
}

// ---------------- fused attention + fc-mix + LayerNorm ----------------
// Block: 256 threads = 8 warps = 2 pixels x 4 dilations. Attention per warp
// into smem, then fc mixing + residual + LN(64) per pixel, write y2 (rounded).
__global__ __launch_bounds__(256) void attn_ln_k(
    const float* __restrict__ qkv,
    const float* __restrict__ fcw, const float* __restrict__ fcb,
    const float* __restrict__ lng, const float* __restrict__ lnb,
    float* __restrict__ y2)
{
    __shared__ float sOut[512];       // [2 pixels][4 dil][64 ch]
    __shared__ float ssum[8], ssq[8];

    const int tid  = threadIdx.x;
    const int wid  = tid >> 5;
    const int lane = tid & 31;
    const int pp   = wid >> 2;        // 0/1
    const int dil  = wid & 3;
    const int pix  = blockIdx.x * 2 + pp;
    const int b    = pix / HW;
    const int pixl = pix - b * HW;
    const int y    = pixl / Ww;
    const int x    = pixl - y * Ww;
    const int r    = 1 << dil;

    const float* base = qkv + (size_t)b * HW * 768;
    const float* qp = base + (size_t)pixl * 768 + dil * 64;
    const float q0 = qp[lane], q1 = qp[lane + 32];

    float sc[9];
#pragma unroll
    for (int j = 0; j < 9; j++){
        const int yy = y + (j/3 - 1) * r;
        const int xx = x + (j%3 - 1) * r;
        float s = 0.f;
        if (yy >= 0 && yy < Hh && xx >= 0 && xx < Ww){
            const float* kp = base + (size_t)(yy*Ww + xx)*768 + 256 + dil*64;
            s = q0 * kp[lane] + q1 * kp[lane + 32];
        }
#pragma unroll
        for (int o = 16; o > 0; o >>= 1) s += __shfl_xor_sync(0xffffffffu, s, o);
        sc[j] = s * 0.125f;
    }
    float mx = sc[0];
#pragma unroll
    for (int j = 1; j < 9; j++) mx = fmaxf(mx, sc[j]);
    float p[9], sum = 0.f;
#pragma unroll
    for (int j = 0; j < 9; j++){ p[j] = expf(sc[j] - mx); sum += p[j]; }
    const float inv = 1.f / sum;

    float a0 = 0.f, a1 = 0.f;
#pragma unroll
    for (int j = 0; j < 9; j++){
        const int yy = y + (j/3 - 1) * r;
        const int xx = x + (j%3 - 1) * r;
        if (yy >= 0 && yy < Hh && xx >= 0 && xx < Ww){
            const float* vp = base + (size_t)(yy*Ww + xx)*768 + 512 + dil*64;
            a0 += p[j] * vp[lane];
            a1 += p[j] * vp[lane + 32];
        }
    }
    float* op = sOut + pp*256 + dil*64;
    op[lane]      = a0 * inv;
    op[lane + 32] = a1 * inv;
    __syncthreads();

    // fc mix + residual + LN, pixel by pixel (all 256 threads per pixel)
    const int t = tid >> 6;           // dilation slot 0..3
    const int c = tid & 63;
    const int w = tid >> 5;
#pragma unroll
    for (int q = 0; q < 2; q++){
        const float* sp = sOut + q*256;
        const float s0 = sp[c], s1 = sp[64 + c], s2 = sp[128 + c], s3 = sp[192 + c];
        const float own = (t == 0) ? s0 : (t == 1) ? s1 : (t == 2) ? s2 : s3;
        float f = fcw[t*4+0]*s0 + fcw[t*4+1]*s1 + fcw[t*4+2]*s2 + fcw[t*4+3]*s3
                  + fcb[t] + own;

        float sm = f, sq = f*f;
#pragma unroll
        for (int o = 16; o > 0; o >>= 1){
            sm += __shfl_xor_sync(0xffffffffu, sm, o);
            sq += __shfl_xor_sync(0xffffffffu, sq, o);
        }
        if ((tid & 31) == 0){ ssum[w] = sm; ssq[w] = sq; }
        __syncthreads();
        const float tot  = ssum[2*t] + ssum[2*t+1];
        const float totq = ssq[2*t]  + ssq[2*t+1];
        const float mu  = tot * (1.f/64.f);
        const float var = totq * (1.f/64.f) - mu*mu;
        const float yv = (f - mu) * rsqrtf(var + EPSF) * lng[c] + lnb[c];
        y2[(size_t)(blockIdx.x*2 + q)*256 + tid] = rna(yv);
        __syncthreads();
    }
}

// ---------------- launch ----------------
extern "C" void kernel_launch(void* const* d_in, const int* in_sizes, int n_in,
                              void* d_out, int out_size)
{
    const float* x      = (const float*)d_in[0];
    const float* qkv_w  = (const float*)d_in[1];
    const float* qkv_b  = (const float*)d_in[2];
    const float* fc_w   = (const float*)d_in[3];
    const float* fc_b   = (const float*)d_in[4];
    const float* ln_g   = (const float*)d_in[5];
    const float* ln_b   = (const float*)d_in[6];
    const float* proj_w = (const float*)d_in[7];
    const float* proj_b = (const float*)d_in[8];
    const float* w1     = (const float*)d_in[9];
    const float* bn1_g  = (const float*)d_in[10];
    const float* bn1_b  = (const float*)d_in[11];
    const float* bn1_m  = (const float*)d_in[12];
    const float* bn1_v  = (const float*)d_in[13];
    const float* w2     = (const float*)d_in[14];
    const float* bn2_g  = (const float*)d_in[15];
    const float* bn2_b  = (const float*)d_in[16];
    const float* bn2_m  = (const float*)d_in[17];
    const float* bn2_v  = (const float*)d_in[18];
    float* out = (float*)d_out;

    float *xT, *xTf, *qkv, *y2, *x1r, *x1f, *hb, *gw;
    cudaGetSymbolAddress((void**)&xT,  g_xT);
    cudaGetSymbolAddress((void**)&xTf, g_xTf);
    cudaGetSymbolAddress((void**)&qkv, g_qkv);
    cudaGetSymbolAddress((void**)&y2,  g_y2);
    cudaGetSymbolAddress((void**)&x1r, g_x1r);
    cudaGetSymbolAddress((void**)&x1f, g_x1f);
    cudaGetSymbolAddress((void**)&hb,  g_h);
    cudaGetSymbolAddress((void**)&gw,  g_w);

    cudaFuncSetAttribute(gemm_mma<0>, cudaFuncAttributeMaxDynamicSharedMemorySize, SMEM_BYTES);
    cudaFuncSetAttribute(gemm_mma<1>, cudaFuncAttributeMaxDynamicSharedMemorySize, SMEM_BYTES);
    cudaFuncSetAttribute(gemm_mma<2>, cudaFuncAttributeMaxDynamicSharedMemorySize, SMEM_BYTES);
    cudaFuncSetAttribute(gemm_mma<3>, cudaFuncAttributeMaxDynamicSharedMemorySize, SMEM_BYTES);

    roundw_k<<<2048, 256>>>(qkv_w, proj_w, w1, w2, gw);
    transpose_k<<<dim3(HW/32, C_/32, B_), dim3(32, 8)>>>(x, xT, xTf);

    // 1) qkv = xT @ qkv_w^T + b : [51200][768]
    gemm_mma<0><<<dim3(6, 400), 256, SMEM_BYTES>>>(
        xT, gw, qkv, nullptr, 256, 768, qkv_b, nullptr, nullptr, nullptr, nullptr, nullptr);

    // 2+3) attention + fc mix + LN (fused)
    attn_ln_k<<<NPIX/2, 256>>>(qkv, fc_w, fc_b, ln_g, ln_b, y2);

    // 4) x1 = y2 @ proj_w^T + proj_b + x : rounded -> x1r, full -> x1f
    gemm_mma<1><<<dim3(2, 400), 256, SMEM_BYTES>>>(
        y2, gw + 196608, x1r, x1f, 256, 256, proj_b, xTf, nullptr, nullptr, nullptr, nullptr);

    // 5) h = silu(bn1(x1 @ w1^T)) : [51200][512]
    gemm_mma<2><<<dim3(4, 400), 256, SMEM_BYTES>>>(
        x1r, gw + 262144, hb, nullptr, 256, 512, nullptr, nullptr, bn1_g, bn1_b, bn1_m, bn1_v);

    // 6) out = x1 + bn2(h @ w2^T) -> [B][C][HW]
    gemm_mma<3><<<dim3(2, 400), 256, SMEM_BYTES>>>(
        hb, gw + 393216, out, nullptr, 512, 256, nullptr, x1f, bn2_g, bn2_b, bn2_m, bn2_v);
}

// round 5
// speedup vs baseline: 4.0951x; 1.0319x over previous
#include <cuda_runtime.h>
#include <cstdint>
#include <math.h>

#define B_  8
#define C_  256
#define Hh  80
#define Ww  80
#define HW  6400
#define NPIX 51200
#define EPSF 1e-5f

#define KC 32
#define STAGES 3
#define TSTR 36                 // smem row stride in floats (144B, 16B-aligned)
#define ASZ (128*TSTR)          // floats per stage per operand
#define SMEM_BYTES (STAGES*2*ASZ*4)   // 3 stages x (A+B) = 110592 B

// ---------------- scratch ----------------
__device__ float g_xT [(size_t)NPIX*256];   // tf32-rounded (GEMM A)
__device__ float g_qkv[(size_t)NPIX*768];
__device__ float g_y2 [(size_t)NPIX*256];
__device__ float g_x1r[(size_t)NPIX*256];   // tf32-rounded (GEMM A)
__device__ float g_x1f[(size_t)NPIX*256];   // full fp32 (residual)
__device__ float g_h  [(size_t)NPIX*512];
__device__ float g_w  [524288];             // rounded weights: qkvw|projw|w1|w2

// ---------------- helpers ----------------
__device__ __forceinline__ float rna(float x){ float r; asm("cvt.rna.tf32.f32 %0, %1;" : "=f"(r) : "f"(x)); return r; }
__device__ __forceinline__ uint32_t s2u(const void* p){
    uint32_t a; asm("{ .reg .u64 t; cvta.to.shared.u64 t, %1; cvt.u32.u64 %0, t; }" : "=r"(a) : "l"(p)); return a;
}
#define CPA16(d,s) asm volatile("cp.async.cg.shared.global [%0], [%1], 16;" :: "r"(d), "l"(s))
#define CPCOMMIT() asm volatile("cp.async.commit_group;" ::: "memory")
#define CPWAIT(n)  asm volatile("cp.async.wait_group %0;" :: "n"(n) : "memory")

__device__ __forceinline__ void mma8(float* d, const uint32_t* a, uint32_t b0, uint32_t b1){
    asm volatile("mma.sync.aligned.m16n8k8.row.col.f32.tf32.tf32.f32 "
        "{%0,%1,%2,%3}, {%4,%5,%6,%7}, {%8,%9}, {%0,%1,%2,%3};"
        : "+f"(d[0]), "+f"(d[1]), "+f"(d[2]), "+f"(d[3])
        : "r"(a[0]), "r"(a[1]), "r"(a[2]), "r"(a[3]), "r"(b0), "r"(b1));
}

// ---------------- tf32 mma.sync GEMM: D[pix, n] = A[pix,:] . Bw[n,:] ----------------
// MODE 0: y = acc + bias[n]                            -> qkv (Cstride 768)
// MODE 1: Cp = rna(acc+bias+resx), Cp2 = full          -> x1r / x1f  (resx = x[b][c][hw])
// MODE 2: y = rna(silu(acc*sc+sh))                     -> h   (Cstride 512)
// MODE 3: y = acc*sc+sh + res -> out[b][n][pixl]       (smem-staged transposed store)
template<int MODE>
__global__ __launch_bounds__(256, 2) void gemm_mma(
    const float* __restrict__ A, const float* __restrict__ Bw,
    float* __restrict__ Cp, float* __restrict__ Cp2, int Ktot, int Cstride,
    const float* __restrict__ bias, const float* __restrict__ res,
    const float* __restrict__ gg, const float* __restrict__ bb,
    const float* __restrict__ mm, const float* __restrict__ vv)
{
    extern __shared__ float smemf[];
    const uint32_t smem_b = s2u(smemf);

    const int tid  = threadIdx.x;
    const int wid  = tid >> 5;
    const int lane = tid & 31;
    const int wm   = wid & 1;        // 2 warps in M
    const int wn   = wid >> 1;       // 4 warps in N
    const int lr   = lane >> 2;      // 0..7
    const int lc   = lane & 3;       // 0..3
    const int m0   = blockIdx.y * 128;
    const int n0   = blockIdx.x * 128;

    float d[4][4][4];
#pragma unroll
    for (int i = 0; i < 4; i++)
#pragma unroll
        for (int j = 0; j < 4; j++)
#pragma unroll
            for (int e = 0; e < 4; e++) d[i][j][e] = 0.f;

    const int nch = Ktot / KC;

    auto load = [&](int cc){
        const int s = cc % STAGES;
        const float* Ab = A + (size_t)m0 * Ktot + cc*KC;
        const uint32_t da = smem_b + (2*s)*ASZ*4;
#pragma unroll
        for (int t = 0; t < 4; t++){
            int i = tid + t*256;
            int r = i >> 3, c = i & 7;
            CPA16(da + r*TSTR*4 + c*16, (const void*)(Ab + (size_t)r*Ktot + c*4));
        }
        const float* Bb = Bw + (size_t)n0 * Ktot + cc*KC;
        const uint32_t db = smem_b + (2*s+1)*ASZ*4;
#pragma unroll
        for (int t = 0; t < 4; t++){
            int i = tid + t*256;
            int r = i >> 3, c = i & 7;
            CPA16(db + r*TSTR*4 + c*16, (const void*)(Bb + (size_t)r*Ktot + c*4));
        }
        CPCOMMIT();
    };

    load(0);
    load(1);

    for (int cc = 0; cc < nch; cc++){
        if (cc + 2 < nch) load(cc + 2);
        const int rem = nch - 1 - cc;
        if (rem >= 2)      CPWAIT(2);
        else if (rem == 1) CPWAIT(1);
        else               CPWAIT(0);
        __syncthreads();

        const int s = cc % STAGES;
        const uint32_t* au = (const uint32_t*)(smemf + (2*s)*ASZ)
                             + (wm*64 + lr)*TSTR + lc;
        const uint32_t* bu = (const uint32_t*)(smemf + (2*s+1)*ASZ)
                             + (wn*32 + lr)*TSTR + lc;
#pragma unroll
        for (int kk = 0; kk < 4; kk++){
            uint32_t af[4][4];
#pragma unroll
            for (int mi = 0; mi < 4; mi++){
                const uint32_t* p = au + mi*16*TSTR + kk*8;
                af[mi][0] = p[0];
                af[mi][1] = p[8*TSTR];
                af[mi][2] = p[4];
                af[mi][3] = p[8*TSTR + 4];
            }
#pragma unroll
            for (int ni = 0; ni < 4; ni++){
                const uint32_t* p = bu + ni*8*TSTR + kk*8;
                uint32_t b0 = p[0], b1 = p[4];
#pragma unroll
                for (int mi = 0; mi < 4; mi++)
                    mma8(d[mi][ni], af[mi], b0, b1);
            }
        }
        __syncthreads();
    }

    // ---------------- epilogue ----------------
    const int lc2 = lc * 2;

    if (MODE != 3){
        float bv0[4], bv1[4], sc0[4], sc1[4], sh0[4], sh1[4];
#pragma unroll
        for (int ni = 0; ni < 4; ni++){
            const int gc = n0 + wn*32 + ni*8 + lc2;
            if (MODE <= 1){ bv0[ni] = bias[gc]; bv1[ni] = bias[gc+1]; }
            if (MODE == 2){
                float i0 = gg[gc]   * rsqrtf(vv[gc]   + EPSF);
                float i1 = gg[gc+1] * rsqrtf(vv[gc+1] + EPSF);
                sc0[ni] = i0; sh0[ni] = bb[gc]   - mm[gc]  *i0;
                sc1[ni] = i1; sh1[ni] = bb[gc+1] - mm[gc+1]*i1;
            }
        }
        const int bidx  = (MODE == 1) ? m0 / HW : 0;
        const int pixl0 = (MODE == 1) ? m0 - bidx*HW : 0;
        const float* xb = (MODE == 1) ? res + (size_t)bidx*C_*HW : (const float*)0;
#pragma unroll
        for (int mi = 0; mi < 4; mi++){
#pragma unroll
            for (int rr = 0; rr < 2; rr++){
                const int rl = wm*64 + mi*16 + lr + rr*8;
                const int r  = m0 + rl;
                float* crow = Cp + (size_t)r*Cstride + n0 + wn*32;
                float* crow2 = (MODE == 1) ? Cp2 + (size_t)r*256 + n0 + wn*32 : (float*)0;
                const int pixl = pixl0 + rl;
#pragma unroll
                for (int ni = 0; ni < 4; ni++){
                    const int c = ni*8 + lc2;
                    float v0 = d[mi][ni][rr*2+0];
                    float v1 = d[mi][ni][rr*2+1];
                    if (MODE == 0){
                        v0 += bv0[ni]; v1 += bv1[ni];
                        *(float2*)(crow + c) = make_float2(v0, v1);
                    } else if (MODE == 1){
                        const int gc = n0 + wn*32 + c;
                        v0 += bv0[ni] + xb[(size_t)gc*HW + pixl];
                        v1 += bv1[ni] + xb[(size_t)(gc+1)*HW + pixl];
                        *(float2*)(crow2 + c) = make_float2(v0, v1);
                        *(float2*)(crow  + c) = make_float2(rna(v0), rna(v1));
                    } else { // MODE 2
                        v0 = v0*sc0[ni] + sh0[ni];
                        v1 = v1*sc1[ni] + sh1[ni];
                        v0 = v0 * __frcp_rn(1.f + __expf(-v0));
                        v1 = v1 * __frcp_rn(1.f + __expf(-v1));
                        *(float2*)(crow + c) = make_float2(rna(v0), rna(v1));
                    }
                }
            }
        }
    } else {
        // MODE 3: bn2 + residual, then smem-transposed coalesced store to [b][c][hw]
        __syncthreads();
        float* stg = smemf + wid * (64*33);
#pragma unroll
        for (int ni = 0; ni < 4; ni++){
            const int gc = n0 + wn*32 + ni*8 + lc2;
            const float i0 = gg[gc]   * rsqrtf(vv[gc]   + EPSF);
            const float i1 = gg[gc+1] * rsqrtf(vv[gc+1] + EPSF);
            const float s0 = bb[gc]   - mm[gc]  *i0;
            const float s1 = bb[gc+1] - mm[gc+1]*i1;
#pragma unroll
            for (int mi = 0; mi < 4; mi++){
#pragma unroll
                for (int rr = 0; rr < 2; rr++){
                    const int lrow = mi*16 + lr + rr*8;
                    const int grow = m0 + wm*64 + lrow;
                    const float* rp = res + (size_t)grow*256 + gc;
                    stg[lrow*33 + ni*8 + lc2]     = d[mi][ni][rr*2+0]*i0 + s0 + rp[0];
                    stg[lrow*33 + ni*8 + lc2 + 1] = d[mi][ni][rr*2+1]*i1 + s1 + rp[1];
                }
            }
        }
        __syncwarp();
        const int pix0 = m0 + wm*64;
        const int bidx = pix0 / HW;
        const int pixl = pix0 - bidx*HW;
        float* ob = Cp + (size_t)bidx*C_*HW + pixl;
#pragma unroll
        for (int n = 0; n < 32; n++){
            const int gc = n0 + wn*32 + n;
            ob[(size_t)gc*HW + lane]      = stg[lane*33 + n];
            ob[(size_t)gc*HW + lane + 32] = stg[(lane+32)*33 + n];
        }
    }
}

// ---------------- transpose x [B][C][HW] -> xT (tf32-rounded) ----------------
__global__ __launch_bounds__(256) void transpose_k(const float* __restrict__ x,
                                                   float* __restrict__ xT)
{
    __shared__ float t[32][33];
    const int b = blockIdx.z;
    const int hw0 = blockIdx.x * 32, c0 = blockIdx.y * 32;
    const int tx = threadIdx.x, ty = threadIdx.y;
#pragma unroll
    for (int i = 0; i < 4; i++){
        int c = c0 + ty + i*8;
        t[ty + i*8][tx] = x[(size_t)b*C_*HW + (size_t)c*HW + hw0 + tx];
    }
    __syncthreads();
#pragma unroll
    for (int i = 0; i < 4; i++){
        int hw = hw0 + ty + i*8;
        xT[(size_t)(b*HW + hw)*256 + c0 + tx] = rna(t[tx][ty + i*8]);
    }
}

// ---------------- round weights ----------------
__global__ __launch_bounds__(256) void roundw_k(
    const float* __restrict__ qkvw, const float* __restrict__ projw,
    const float* __restrict__ w1, const float* __restrict__ w2, float* __restrict__ gw)
{
    int i = blockIdx.x * 256 + threadIdx.x;
    float v;
    if (i < 196608)      v = qkvw[i];
    else if (i < 262144) v = projw[i - 196608];
    else if (i < 393216) v = w1[i - 262144];
    else                 v = w2[i - 393216];
    gw[i] = rna(v);
}

// ---------------- fused attention + fc-mix + LayerNorm ----------------
// Block: 256 threads = 8 warps = 2 pixels x 4 dilations.
// Channel mapping: lane handles channels {2*lane, 2*lane+1} (float2 everywhere).
__global__ __launch_bounds__(256) void attn_ln_k(
    const float* __restrict__ qkv,
    const float* __restrict__ fcw, const float* __restrict__ fcb,
    const float* __restrict__ lng, const float* __restrict__ lnb,
    float* __restrict__ y2)
{
    __shared__ float sOut[512];       // [2 pixels][4 dil][64 ch]
    __shared__ float ssum[8], ssq[8];

    const int tid  = threadIdx.x;
    const int wid  = tid >> 5;
    const int lane = tid & 31;
    const int pp   = wid >> 2;        // 0/1
    const int dil  = wid & 3;
    const int pix  = blockIdx.x * 2 + pp;
    const int b    = pix / HW;
    const int pixl = pix - b * HW;
    const int y    = pixl / Ww;
    const int x    = pixl - y * Ww;
    const int r    = 1 << dil;

    const float* base = qkv + (size_t)b * HW * 768 + dil*64 + 2*lane;

    // precompute neighbor offsets + validity once
    int offs[9]; unsigned vm = 0;
#pragma unroll
    for (int j = 0; j < 9; j++){
        const int yy = y + (j/3 - 1) * r;
        const int xx = x + (j%3 - 1) * r;
        offs[j] = (yy*Ww + xx) * 768;
        if ((unsigned)yy < (unsigned)Hh && (unsigned)xx < (unsigned)Ww) vm |= 1u << j;
    }

    const float2 q = *(const float2*)(base + pixl*768);

    float sc[9];
#pragma unroll
    for (int j = 0; j < 9; j++){
        float s = 0.f;
        if (vm & (1u << j)){
            const float2 kv = *(const float2*)(base + offs[j] + 256);
            s = q.x*kv.x + q.y*kv.y;
        }
#pragma unroll
        for (int o = 16; o > 0; o >>= 1) s += __shfl_xor_sync(0xffffffffu, s, o);
        sc[j] = s * 0.125f;
    }

    float mx = sc[0];
#pragma unroll
    for (int j = 1; j < 9; j++) mx = fmaxf(mx, sc[j]);
    float p[9], sum = 0.f;
#pragma unroll
    for (int j = 0; j < 9; j++){ p[j] = __expf(sc[j] - mx); sum += p[j]; }
    const float inv = __frcp_rn(sum);

    float a0 = 0.f, a1 = 0.f;
#pragma unroll
    for (int j = 0; j < 9; j++){
        if (vm & (1u << j)){
            const float2 vv = *(const float2*)(base + offs[j] + 512);
            a0 += p[j] * vv.x;
            a1 += p[j] * vv.y;
        }
    }
    *(float2*)(sOut + pp*256 + dil*64 + 2*lane) = make_float2(a0*inv, a1*inv);
    __syncthreads();

    // fc mix + residual + LN(64), pixel by pixel (all 256 threads per pixel)
    const int t = tid >> 6;           // dilation slot 0..3
    const int c = tid & 63;
    const int w = tid >> 5;
#pragma unroll
    for (int qq = 0; qq < 2; qq++){
        const float* sp = sOut + qq*256;
        const float s0 = sp[c], s1 = sp[64 + c], s2 = sp[128 + c], s3 = sp[192 + c];
        const float own = (t == 0) ? s0 : (t == 1) ? s1 : (t == 2) ? s2 : s3;
        float f = fcw[t*4+0]*s0 + fcw[t*4+1]*s1 + fcw[t*4+2]*s2 + fcw[t*4+3]*s3
                  + fcb[t] + own;

        float sm = f, sq = f*f;
#pragma unroll
        for (int o = 16; o > 0; o >>= 1){
            sm += __shfl_xor_sync(0xffffffffu, sm, o);
            sq += __shfl_xor_sync(0xffffffffu, sq, o);
        }
        if ((tid & 31) == 0){ ssum[w] = sm; ssq[w] = sq; }
        __syncthreads();
        const float tot  = ssum[2*t] + ssum[2*t+1];
        const float totq = ssq[2*t]  + ssq[2*t+1];
        const float mu  = tot * (1.f/64.f);
        const float var = totq * (1.f/64.f) - mu*mu;
        const float yv = (f - mu) * rsqrtf(var + EPSF) * lng[c] + lnb[c];
        y2[(size_t)(blockIdx.x*2 + qq)*256 + tid] = rna(yv);
        __syncthreads();
    }
}

// ---------------- launch ----------------
extern "C" void kernel_launch(void* const* d_in, const int* in_sizes, int n_in,
                              void* d_out, int out_size)
{
    const float* x      = (const float*)d_in[0];
    const float* qkv_w  = (const float*)d_in[1];
    const float* qkv_b  = (const float*)d_in[2];
    const float* fc_w   = (const float*)d_in[3];
    const float* fc_b   = (const float*)d_in[4];
    const float* ln_g   = (const float*)d_in[5];
    const float* ln_b   = (const float*)d_in[6];
    const float* proj_w = (const float*)d_in[7];
    const float* proj_b = (const float*)d_in[8];
    const float* w1     = (const float*)d_in[9];
    const float* bn1_g  = (const float*)d_in[10];
    const float* bn1_b  = (const float*)d_in[11];
    const float* bn1_m  = (const float*)d_in[12];
    const float* bn1_v  = (const float*)d_in[13];
    const float* w2     = (const float*)d_in[14];
    const float* bn2_g  = (const float*)d_in[15];
    const float* bn2_b  = (const float*)d_in[16];
    const float* bn2_m  = (const float*)d_in[17];
    const float* bn2_v  = (const float*)d_in[18];
    float* out = (float*)d_out;

    float *xT, *qkv, *y2, *x1r, *x1f, *hb, *gw;
    cudaGetSymbolAddress((void**)&xT,  g_xT);
    cudaGetSymbolAddress((void**)&qkv, g_qkv);
    cudaGetSymbolAddress((void**)&y2,  g_y2);
    cudaGetSymbolAddress((void**)&x1r, g_x1r);
    cudaGetSymbolAddress((void**)&x1f, g_x1f);
    cudaGetSymbolAddress((void**)&hb,  g_h);
    cudaGetSymbolAddress((void**)&gw,  g_w);

    cudaFuncSetAttribute(gemm_mma<0>, cudaFuncAttributeMaxDynamicSharedMemorySize, SMEM_BYTES);
    cudaFuncSetAttribute(gemm_mma<1>, cudaFuncAttributeMaxDynamicSharedMemorySize, SMEM_BYTES);
    cudaFuncSetAttribute(gemm_mma<2>, cudaFuncAttributeMaxDynamicSharedMemorySize, SMEM_BYTES);
    cudaFuncSetAttribute(gemm_mma<3>, cudaFuncAttributeMaxDynamicSharedMemorySize, SMEM_BYTES);

    roundw_k<<<2048, 256>>>(qkv_w, proj_w, w1, w2, gw);
    transpose_k<<<dim3(HW/32, C_/32, B_), dim3(32, 8)>>>(x, xT);

    // 1) qkv = xT @ qkv_w^T + b : [51200][768]
    gemm_mma<0><<<dim3(6, 400), 256, SMEM_BYTES>>>(
        xT, gw, qkv, nullptr, 256, 768, qkv_b, nullptr, nullptr, nullptr, nullptr, nullptr);

    // 2+3) attention + fc mix + LN (fused)
    attn_ln_k<<<NPIX/2, 256>>>(qkv, fc_w, fc_b, ln_g, ln_b, y2);

    // 4) x1 = y2 @ proj_w^T + proj_b + x : rounded -> x1r, full -> x1f (residual read from x)
    gemm_mma<1><<<dim3(2, 400), 256, SMEM_BYTES>>>(
        y2, gw + 196608, x1r, x1f, 256, 256, proj_b, x, nullptr, nullptr, nullptr, nullptr);

    // 5) h = silu(bn1(x1 @ w1^T)) : [51200][512]
    gemm_mma<2><<<dim3(4, 400), 256, SMEM_BYTES>>>(
        x1r, gw + 262144, hb, nullptr, 256, 512, nullptr, nullptr, bn1_g, bn1_b, bn1_m, bn1_v);

    // 6) out = x1 + bn2(h @ w2^T) -> [B][C][HW]
    gemm_mma<3><<<dim3(2, 400), 256, SMEM_BYTES>>>(
        hb, gw + 393216, out, nullptr, 512, 256, nullptr, x1f, bn2_g, bn2_b, bn2_m, bn2_v);
}

// round 6
// speedup vs baseline: 4.4552x; 1.0879x over previous
#include <cuda_runtime.h>
#include <cstdint>
#include <math.h>

#define B_  8
#define C_  256
#define Hh  80
#define Ww  80
#define HW  6400
#define NPIX 51200
#define EPSF 1e-5f

#define KC 32
#define STAGES 3
#define TSTR 36                 // smem row stride in floats (144B): LDSM conflict-free
#define ASZ (128*TSTR)          // floats per stage per operand
#define SMEM_BYTES (STAGES*2*ASZ*4)   // 110592 B

// ---------------- scratch ----------------
__device__ float g_xT [(size_t)NPIX*256];
__device__ float g_qkv[(size_t)NPIX*768];
__device__ float g_y2 [(size_t)NPIX*256];
__device__ float g_x1r[(size_t)NPIX*256];
__device__ float g_x1f[(size_t)NPIX*256];
__device__ float g_h  [(size_t)NPIX*512];
__device__ float g_w  [524288];

// ---------------- helpers ----------------
__device__ __forceinline__ float rna(float x){ float r; asm("cvt.rna.tf32.f32 %0, %1;" : "=f"(r) : "f"(x)); return r; }
__device__ __forceinline__ uint32_t s2u(const void* p){
    uint32_t a; asm("{ .reg .u64 t; cvta.to.shared.u64 t, %1; cvt.u32.u64 %0, t; }" : "=r"(a) : "l"(p)); return a;
}
#define CPA16(d,s) asm volatile("cp.async.cg.shared.global [%0], [%1], 16;" :: "r"(d), "l"(s))
#define CPCOMMIT() asm volatile("cp.async.commit_group;" ::: "memory")
#define CPWAIT(n)  asm volatile("cp.async.wait_group %0;" :: "n"(n) : "memory")
#define LDSM4(r0,r1,r2,r3,a) \
    asm volatile("ldmatrix.sync.aligned.m8n8.x4.shared.b16 {%0,%1,%2,%3}, [%4];" \
        : "=r"(r0), "=r"(r1), "=r"(r2), "=r"(r3) : "r"(a))

__device__ __forceinline__ void mma8(float* d, const uint32_t* a, uint32_t b0, uint32_t b1){
    asm volatile("mma.sync.aligned.m16n8k8.row.col.f32.tf32.tf32.f32 "
        "{%0,%1,%2,%3}, {%4,%5,%6,%7}, {%8,%9}, {%0,%1,%2,%3};"
        : "+f"(d[0]), "+f"(d[1]), "+f"(d[2]), "+f"(d[3])
        : "r"(a[0]), "r"(a[1]), "r"(a[2]), "r"(a[3]), "r"(b0), "r"(b1));
}

// ---------------- tf32 mma.sync GEMM (LDSM fragments) ----------------
// MODE 0: y = acc + bias[n]                            -> qkv (Cstride 768)
// MODE 1: Cp = rna(acc+bias+resx), Cp2 = full          -> x1r / x1f  (resx = x[b][c][hw])
// MODE 2: y = rna(silu(acc*sc+sh))                     -> h   (Cstride 512)
// MODE 3: y = acc*sc+sh + res -> out[b][n][pixl]       (smem-staged transposed store)
template<int MODE>
__global__ __launch_bounds__(256, 2) void gemm_mma(
    const float* __restrict__ A, const float* __restrict__ Bw,
    float* __restrict__ Cp, float* __restrict__ Cp2, int Ktot, int Cstride,
    const float* __restrict__ bias, const float* __restrict__ res,
    const float* __restrict__ gg, const float* __restrict__ bb,
    const float* __restrict__ mm, const float* __restrict__ vv)
{
    extern __shared__ float smemf[];
    const uint32_t smem_b = s2u(smemf);

    const int tid  = threadIdx.x;
    const int wid  = tid >> 5;
    const int lane = tid & 31;
    const int wm   = wid & 1;
    const int wn   = wid >> 1;
    const int lr   = lane >> 2;
    const int lc   = lane & 3;
    const int m0   = blockIdx.y * 128;
    const int n0   = blockIdx.x * 128;

    // LDSM per-thread byte offsets within a stage
    const uint32_t aoff = (uint32_t)(((wm*64 + ((lane>>3)&1)*8 + (lane&7))*TSTR + (lane>>4)*4) * 4);
    const uint32_t boff = (uint32_t)(((wn*32 + (lane>>4)*8 + (lane&7))*TSTR + ((lane>>3)&1)*4) * 4);

    float d[4][4][4];
#pragma unroll
    for (int i = 0; i < 4; i++)
#pragma unroll
        for (int j = 0; j < 4; j++)
#pragma unroll
            for (int e = 0; e < 4; e++) d[i][j][e] = 0.f;

    const int nch = Ktot / KC;

    auto load = [&](int cc){
        const int s = cc % STAGES;
        const float* Ab = A + (size_t)m0 * Ktot + cc*KC;
        const uint32_t da = smem_b + (2*s)*ASZ*4;
#pragma unroll
        for (int t = 0; t < 4; t++){
            int i = tid + t*256;
            int r = i >> 3, c = i & 7;
            CPA16(da + r*TSTR*4 + c*16, (const void*)(Ab + (size_t)r*Ktot + c*4));
        }
        const float* Bb = Bw + (size_t)n0 * Ktot + cc*KC;
        const uint32_t db = smem_b + (2*s+1)*ASZ*4;
#pragma unroll
        for (int t = 0; t < 4; t++){
            int i = tid + t*256;
            int r = i >> 3, c = i & 7;
            CPA16(db + r*TSTR*4 + c*16, (const void*)(Bb + (size_t)r*Ktot + c*4));
        }
        CPCOMMIT();
    };

    load(0);
    load(1);

    for (int cc = 0; cc < nch; cc++){
        if (cc + 2 < nch) load(cc + 2);
        const int rem = nch - 1 - cc;
        if (rem >= 2)      CPWAIT(2);
        else if (rem == 1) CPWAIT(1);
        else               CPWAIT(0);
        __syncthreads();

        const int s = cc % STAGES;
        const uint32_t aBase = smem_b + (2*s)*ASZ*4 + aoff;
        const uint32_t bBase = smem_b + (2*s+1)*ASZ*4 + boff;
#pragma unroll
        for (int kk = 0; kk < 4; kk++){
            uint32_t a[4][4], bf[2][4];
#pragma unroll
            for (int mi = 0; mi < 4; mi++)
                LDSM4(a[mi][0], a[mi][1], a[mi][2], a[mi][3],
                      aBase + mi*(16*TSTR*4) + kk*32);
#pragma unroll
            for (int np = 0; np < 2; np++)
                LDSM4(bf[np][0], bf[np][1], bf[np][2], bf[np][3],
                      bBase + np*(16*TSTR*4) + kk*32);
#pragma unroll
            for (int np = 0; np < 2; np++)
#pragma unroll
                for (int mi = 0; mi < 4; mi++){
                    mma8(d[mi][2*np],   a[mi], bf[np][0], bf[np][1]);
                    mma8(d[mi][2*np+1], a[mi], bf[np][2], bf[np][3]);
                }
        }
        __syncthreads();
    }

    // ---------------- epilogue ----------------
    const int lc2 = lc * 2;

    if (MODE != 3){
        float bv0[4], bv1[4], sc0[4], sc1[4], sh0[4], sh1[4];
#pragma unroll
        for (int ni = 0; ni < 4; ni++){
            const int gc = n0 + wn*32 + ni*8 + lc2;
            if (MODE <= 1){ bv0[ni] = bias[gc]; bv1[ni] = bias[gc+1]; }
            if (MODE == 2){
                float i0 = gg[gc]   * rsqrtf(vv[gc]   + EPSF);
                float i1 = gg[gc+1] * rsqrtf(vv[gc+1] + EPSF);
                sc0[ni] = i0; sh0[ni] = bb[gc]   - mm[gc]  *i0;
                sc1[ni] = i1; sh1[ni] = bb[gc+1] - mm[gc+1]*i1;
            }
        }
        const int bidx  = (MODE == 1) ? m0 / HW : 0;
        const int pixl0 = (MODE == 1) ? m0 - bidx*HW : 0;
        const float* xb = (MODE == 1) ? res + (size_t)bidx*C_*HW : (const float*)0;
#pragma unroll
        for (int mi = 0; mi < 4; mi++){
#pragma unroll
            for (int rr = 0; rr < 2; rr++){
                const int rl = wm*64 + mi*16 + lr + rr*8;
                const int r  = m0 + rl;
                float* crow = Cp + (size_t)r*Cstride + n0 + wn*32;
                float* crow2 = (MODE == 1) ? Cp2 + (size_t)r*256 + n0 + wn*32 : (float*)0;
                const int pixl = pixl0 + rl;
#pragma unroll
                for (int ni = 0; ni < 4; ni++){
                    const int c = ni*8 + lc2;
                    float v0 = d[mi][ni][rr*2+0];
                    float v1 = d[mi][ni][rr*2+1];
                    if (MODE == 0){
                        v0 += bv0[ni]; v1 += bv1[ni];
                        *(float2*)(crow + c) = make_float2(v0, v1);
                    } else if (MODE == 1){
                        const int gc = n0 + wn*32 + c;
                        v0 += bv0[ni] + xb[(size_t)gc*HW + pixl];
                        v1 += bv1[ni] + xb[(size_t)(gc+1)*HW + pixl];
                        *(float2*)(crow2 + c) = make_float2(v0, v1);
                        *(float2*)(crow  + c) = make_float2(rna(v0), rna(v1));
                    } else { // MODE 2
                        v0 = v0*sc0[ni] + sh0[ni];
                        v1 = v1*sc1[ni] + sh1[ni];
                        v0 = v0 * __frcp_rn(1.f + __expf(-v0));
                        v1 = v1 * __frcp_rn(1.f + __expf(-v1));
                        *(float2*)(crow + c) = make_float2(rna(v0), rna(v1));
                    }
                }
            }
        }
    } else {
        // MODE 3: bn2 + residual, smem-transposed coalesced store to [b][c][hw]
        __syncthreads();
        float* stg = smemf + wid * (64*33);
#pragma unroll
        for (int ni = 0; ni < 4; ni++){
            const int gc = n0 + wn*32 + ni*8 + lc2;
            const float i0 = gg[gc]   * rsqrtf(vv[gc]   + EPSF);
            const float i1 = gg[gc+1] * rsqrtf(vv[gc+1] + EPSF);
            const float s0 = bb[gc]   - mm[gc]  *i0;
            const float s1 = bb[gc+1] - mm[gc+1]*i1;
#pragma unroll
            for (int mi = 0; mi < 4; mi++){
#pragma unroll
                for (int rr = 0; rr < 2; rr++){
                    const int lrow = mi*16 + lr + rr*8;
                    const int grow = m0 + wm*64 + lrow;
                    const float* rp = res + (size_t)grow*256 + gc;
                    stg[lrow*33 + ni*8 + lc2]     = d[mi][ni][rr*2+0]*i0 + s0 + rp[0];
                    stg[lrow*33 + ni*8 + lc2 + 1] = d[mi][ni][rr*2+1]*i1 + s1 + rp[1];
                }
            }
        }
        __syncwarp();
        const int pix0 = m0 + wm*64;
        const int bidx = pix0 / HW;
        const int pixl = pix0 - bidx*HW;
        float* ob = Cp + (size_t)bidx*C_*HW + pixl;
#pragma unroll
        for (int n = 0; n < 32; n++){
            const int gc = n0 + wn*32 + n;
            ob[(size_t)gc*HW + lane]      = stg[lane*33 + n];
            ob[(size_t)gc*HW + lane + 32] = stg[(lane+32)*33 + n];
        }
    }
}

// ---------------- transpose x [B][C][HW] -> xT (tf32-rounded) ----------------
__global__ __launch_bounds__(256) void transpose_k(const float* __restrict__ x,
                                                   float* __restrict__ xT)
{
    __shared__ float t[32][33];
    const int b = blockIdx.z;
    const int hw0 = blockIdx.x * 32, c0 = blockIdx.y * 32;
    const int tx = threadIdx.x, ty = threadIdx.y;
#pragma unroll
    for (int i = 0; i < 4; i++){
        int c = c0 + ty + i*8;
        t[ty + i*8][tx] = x[(size_t)b*C_*HW + (size_t)c*HW + hw0 + tx];
    }
    __syncthreads();
#pragma unroll
    for (int i = 0; i < 4; i++){
        int hw = hw0 + ty + i*8;
        xT[(size_t)(b*HW + hw)*256 + c0 + tx] = rna(t[tx][ty + i*8]);
    }
}

// ---------------- round weights ----------------
__global__ __launch_bounds__(256) void roundw_k(
    const float* __restrict__ qkvw, const float* __restrict__ projw,
    const float* __restrict__ w1, const float* __restrict__ w2, float* __restrict__ gw)
{
    int i = blockIdx.x * 256 + threadIdx.x;
    float v;
    if (i < 196608)      v = qkvw[i];
    else if (i < 262144) v = projw[i - 196608];
    else if (i < 393216) v = w1[i - 262144];
    else                 v = w2[i - 393216];
    gw[i] = rna(v);
}

// ---------------- fused attention + fc-mix + LayerNorm ----------------
// Block: 256 threads = 8 warps = 4 pixels x 2 dilation-pairs.
// Within a warp: lanes 0-15 = dilation 2*dp, lanes 16-31 = dilation 2*dp+1.
// Each lane covers 4 channels (float4).
__global__ __launch_bounds__(256) void attn_ln_k(
    const float* __restrict__ qkv,
    const float* __restrict__ fcw, const float* __restrict__ fcb,
    const float* __restrict__ lng, const float* __restrict__ lnb,
    float* __restrict__ y2)
{
    __shared__ float sOut[1024];      // [4 pixels][4 dil][64 ch]
    __shared__ float ssum[8], ssq[8];

    const int tid  = threadIdx.x;
    const int wid  = tid >> 5;
    const int lane = tid & 31;
    const int pp   = wid >> 1;        // pixel in block 0..3
    const int dp   = wid & 1;         // dilation pair
    const int dil  = dp*2 + (lane >> 4);
    const int c0   = (lane & 15) * 4;
    const int pix  = blockIdx.x * 4 + pp;
    const int b    = pix / HW;
    const int pixl = pix - b * HW;
    const int y    = pixl / Ww;
    const int x    = pixl - y * Ww;
    const int r    = 1 << dil;

    const float* base = qkv + (size_t)b * HW * 768 + dil*64 + c0;

    int offs[9]; unsigned vm = 0;
#pragma unroll
    for (int j = 0; j < 9; j++){
        const int yy = y + (j/3 - 1) * r;
        const int xx = x + (j%3 - 1) * r;
        offs[j] = (yy*Ww + xx) * 768;
        if ((unsigned)yy < (unsigned)Hh && (unsigned)xx < (unsigned)Ww) vm |= 1u << j;
    }

    const float4 q = *(const float4*)(base + pixl*768);

    float sc[9];
#pragma unroll
    for (int j = 0; j < 9; j++){
        float s = 0.f;
        if (vm & (1u << j)){
            const float4 kv = *(const float4*)(base + offs[j] + 256);
            s = q.x*kv.x + q.y*kv.y + q.z*kv.z + q.w*kv.w;
        }
#pragma unroll
        for (int o = 8; o > 0; o >>= 1) s += __shfl_xor_sync(0xffffffffu, s, o);
        sc[j] = s * 0.125f;
    }

    float mx = sc[0];
#pragma unroll
    for (int j = 1; j < 9; j++) mx = fmaxf(mx, sc[j]);
    float p[9], sum = 0.f;
#pragma unroll
    for (int j = 0; j < 9; j++){ p[j] = __expf(sc[j] - mx); sum += p[j]; }
    const float inv = __frcp_rn(sum);

    float a0 = 0.f, a1 = 0.f, a2 = 0.f, a3 = 0.f;
#pragma unroll
    for (int j = 0; j < 9; j++){
        if (vm & (1u << j)){
            const float4 vv = *(const float4*)(base + offs[j] + 512);
            a0 += p[j] * vv.x;
            a1 += p[j] * vv.y;
            a2 += p[j] * vv.z;
            a3 += p[j] * vv.w;
        }
    }
    *(float4*)(sOut + pp*256 + dil*64 + c0) = make_float4(a0*inv, a1*inv, a2*inv, a3*inv);
    __syncthreads();

    // fc mix + residual + LN(64), pixel by pixel (all 256 threads per pixel)
    const int t = tid >> 6;
    const int c = tid & 63;
    const int w = tid >> 5;
#pragma unroll
    for (int qq = 0; qq < 4; qq++){
        const float* sp = sOut + qq*256;
        const float s0 = sp[c], s1 = sp[64 + c], s2 = sp[128 + c], s3 = sp[192 + c];
        const float own = (t == 0) ? s0 : (t == 1) ? s1 : (t == 2) ? s2 : s3;
        float f = fcw[t*4+0]*s0 + fcw[t*4+1]*s1 + fcw[t*4+2]*s2 + fcw[t*4+3]*s3
                  + fcb[t] + own;

        float sm = f, sq = f*f;
#pragma unroll
        for (int o = 16; o > 0; o >>= 1){
            sm += __shfl_xor_sync(0xffffffffu, sm, o);
            sq += __shfl_xor_sync(0xffffffffu, sq, o);
        }
        if ((tid & 31) == 0){ ssum[w] = sm; ssq[w] = sq; }
        __syncthreads();
        const float tot  = ssum[2*t] + ssum[2*t+1];
        const float totq = ssq[2*t]  + ssq[2*t+1];
        const float mu  = tot * (1.f/64.f);
        const float var = totq * (1.f/64.f) - mu*mu;
        const float yv = (f - mu) * rsqrtf(var + EPSF) * lng[c] + lnb[c];
        y2[(size_t)(blockIdx.x*4 + qq)*256 + tid] = rna(yv);
        __syncthreads();
    }
}

// ---------------- launch ----------------
extern "C" void kernel_launch(void* const* d_in, const int* in_sizes, int n_in,
                              void* d_out, int out_size)
{
    const float* x      = (const float*)d_in[0];
    const float* qkv_w  = (const float*)d_in[1];
    const float* qkv_b  = (const float*)d_in[2];
    const float* fc_w   = (const float*)d_in[3];
    const float* fc_b   = (const float*)d_in[4];
    const float* ln_g   = (const float*)d_in[5];
    const float* ln_b   = (const float*)d_in[6];
    const float* proj_w = (const float*)d_in[7];
    const float* proj_b = (const float*)d_in[8];
    const float* w1     = (const float*)d_in[9];
    const float* bn1_g  = (const float*)d_in[10];
    const float* bn1_b  = (const float*)d_in[11];
    const float* bn1_m  = (const float*)d_in[12];
    const float* bn1_v  = (const float*)d_in[13];
    const float* w2     = (const float*)d_in[14];
    const float* bn2_g  = (const float*)d_in[15];
    const float* bn2_b  = (const float*)d_in[16];
    const float* bn2_m  = (const float*)d_in[17];
    const float* bn2_v  = (const float*)d_in[18];
    float* out = (float*)d_out;

    float *xT, *qkv, *y2, *x1r, *x1f, *hb, *gw;
    cudaGetSymbolAddress((void**)&xT,  g_xT);
    cudaGetSymbolAddress((void**)&qkv, g_qkv);
    cudaGetSymbolAddress((void**)&y2,  g_y2);
    cudaGetSymbolAddress((void**)&x1r, g_x1r);
    cudaGetSymbolAddress((void**)&x1f, g_x1f);
    cudaGetSymbolAddress((void**)&hb,  g_h);
    cudaGetSymbolAddress((void**)&gw,  g_w);

    cudaFuncSetAttribute(gemm_mma<0>, cudaFuncAttributeMaxDynamicSharedMemorySize, SMEM_BYTES);
    cudaFuncSetAttribute(gemm_mma<1>, cudaFuncAttributeMaxDynamicSharedMemorySize, SMEM_BYTES);
    cudaFuncSetAttribute(gemm_mma<2>, cudaFuncAttributeMaxDynamicSharedMemorySize, SMEM_BYTES);
    cudaFuncSetAttribute(gemm_mma<3>, cudaFuncAttributeMaxDynamicSharedMemorySize, SMEM_BYTES);

    roundw_k<<<2048, 256>>>(qkv_w, proj_w, w1, w2, gw);
    transpose_k<<<dim3(HW/32, C_/32, B_), dim3(32, 8)>>>(x, xT);

    // 1) qkv = xT @ qkv_w^T + b : [51200][768]
    gemm_mma<0><<<dim3(6, 400), 256, SMEM_BYTES>>>(
        xT, gw, qkv, nullptr, 256, 768, qkv_b, nullptr, nullptr, nullptr, nullptr, nullptr);

    // 2+3) attention + fc mix + LN (fused)
    attn_ln_k<<<NPIX/4, 256>>>(qkv, fc_w, fc_b, ln_g, ln_b, y2);

    // 4) x1 = y2 @ proj_w^T + proj_b + x
    gemm_mma<1><<<dim3(2, 400), 256, SMEM_BYTES>>>(
        y2, gw + 196608, x1r, x1f, 256, 256, proj_b, x, nullptr, nullptr, nullptr, nullptr);

    // 5) h = silu(bn1(x1 @ w1^T)) : [51200][512]
    gemm_mma<2><<<dim3(4, 400), 256, SMEM_BYTES>>>(
        x1r, gw + 262144, hb, nullptr, 256, 512, nullptr, nullptr, bn1_g, bn1_b, bn1_m, bn1_v);

    // 6) out = x1 + bn2(h @ w2^T) -> [B][C][HW]
    gemm_mma<3><<<dim3(2, 400), 256, SMEM_BYTES>>>(
        hb, gw + 393216, out, nullptr, 512, 256, nullptr, x1f, bn2_g, bn2_b, bn2_m, bn2_v);
}